// round 7
// baseline (speedup 1.0000x reference)
#include <cuda_runtime.h>
#include <cuda_bf16.h>
#include <math.h>
#include <stdint.h>

// Problem constants
#define G_  4
#define S_  512
#define H_  2048
#define V_  151936
#define M_  (G_*S_)              // 2048
#define TOKS (G_*(S_-1))         // 2044
#define NT2 594                  // ceil(V/256) n-tiles of 256 (last is ragged)

// int8 scaling: logits_i32 = (A*512)·(W*1024) -> multiply by 1/524288
#define SA 512.0f
#define SB 1024.0f
#define INV (1.0f/(SA*SB))

// GEMM tiling (int8: K-chunk = 128 elements = 128 bytes/row)
#define BM 128
#define BN 256
#define KT 128
#define NCH (H_/KT)              // 16 k-chunks
#define HB 2048                  // bytes per row (H_ int8)
#define ASTR 144                 // smem bytes per row (pad, conflict-free)
#define A_ST (BM*ASTR)           // 18432
#define B_ST (BN*ASTR)           // 36864
#define STG  (A_ST+B_ST)         // 55296 per stage
#define NSTAGE 3                 // 165888 B dynamic smem

// ---------------- scratch (no allocs -> __device__ globals) ------------------
__device__ signed char g_Wq[(size_t)(V_+128)*HB];  // s8 W (x1024), zero-padded tail
__device__ signed char g_Aq[(size_t)M_*HB];        // s8 hidden (x512)
__device__ float g_pmax[(size_t)NT2*M_];
__device__ float g_psum[(size_t)NT2*M_];
__device__ float g_labeldot[TOKS];
__device__ float g_tokloss[TOKS];

// ---------------- helpers ----------------------------------------------------
__device__ __forceinline__ uint32_t smem_u32(const void* p) {
    uint32_t a;
    asm("{ .reg .u64 t; cvta.to.shared.u64 t, %1; cvt.u32.u64 %0, t; }" : "=r"(a) : "l"(p));
    return a;
}
__device__ __forceinline__ void cp16(uint32_t dst, const void* src) {
    asm volatile("cp.async.cg.shared.global [%0], [%1], 16;"
                 :: "r"(dst), "l"(__cvta_generic_to_global(src)) : "memory");
}
__device__ __forceinline__ void cp_commit() {
    asm volatile("cp.async.commit_group;" ::: "memory");
}
__device__ __forceinline__ void cp_wait1() {
    asm volatile("cp.async.wait_group 1;" ::: "memory");
}
__device__ __forceinline__ void ldmx4(uint32_t* r, uint32_t addr) {
    asm volatile("ldmatrix.sync.aligned.m8n8.x4.shared.b16 {%0,%1,%2,%3}, [%4];"
                 : "=r"(r[0]), "=r"(r[1]), "=r"(r[2]), "=r"(r[3]) : "r"(addr));
}
__device__ __forceinline__ void mma_s8(int* d, const uint32_t* a, uint32_t b0, uint32_t b1) {
    asm volatile(
        "mma.sync.aligned.m16n8k32.row.col.s32.s8.s8.s32 "
        "{%0,%1,%2,%3}, {%4,%5,%6,%7}, {%8,%9}, {%0,%1,%2,%3};"
        : "+r"(d[0]), "+r"(d[1]), "+r"(d[2]), "+r"(d[3])
        : "r"(a[0]), "r"(a[1]), "r"(a[2]), "r"(a[3]), "r"(b0), "r"(b1));
}
__device__ __forceinline__ int q8(float x, float sc) {
    int v = __float2int_rn(x * sc);
    return max(-127, min(127, v));
}
__device__ __forceinline__ unsigned pack4(float a, float b, float c, float d, float sc) {
    return (unsigned)(q8(a,sc) & 0xff) | ((unsigned)(q8(b,sc) & 0xff) << 8) |
           ((unsigned)(q8(c,sc) & 0xff) << 16) | ((unsigned)(q8(d,sc) & 0xff) << 24);
}

// ---------------- fp32 -> int8 conversion ------------------------------------
__global__ void convW_kernel(const float* __restrict__ src) {
    size_t n8 = (size_t)V_*(H_/8);
    size_t stride = (size_t)gridDim.x*blockDim.x;
    const float4* s4 = (const float4*)src;
    uint2* d2 = (uint2*)g_Wq;
    for (size_t i = (size_t)blockIdx.x*blockDim.x + threadIdx.x; i < n8; i += stride) {
        float4 f0 = s4[2*i], f1 = s4[2*i+1];
        uint2 u;
        u.x = pack4(f0.x, f0.y, f0.z, f0.w, SB);
        u.y = pack4(f1.x, f1.y, f1.z, f1.w, SB);
        d2[i] = u;
    }
}
__global__ void convA_kernel(const float* __restrict__ src) {
    size_t i = (size_t)blockIdx.x*blockDim.x + threadIdx.x;
    size_t n8 = (size_t)M_*(H_/8);
    if (i >= n8) return;
    const float4* s4 = (const float4*)src;
    float4 f0 = s4[2*i], f1 = s4[2*i+1];
    uint2 u;
    u.x = pack4(f0.x, f0.y, f0.z, f0.w, SA);
    u.y = pack4(f1.x, f1.y, f1.z, f1.w, SA);
    ((uint2*)g_Aq)[i] = u;
}

// ---------------- GEMM (128x256 int8) + per-tile online softmax partials -----
// 256 threads, 8 warps (2x4), warp tile 64x64, cp.async 3-stage pipeline.
__device__ __forceinline__ void load_stage(uint32_t sbase, int s, int c,
                                           const signed char* gA,
                                           const signed char* gB, int tid) {
    uint32_t sa = sbase + s*STG;
    size_t k0 = (size_t)c*KT;            // byte offset (int8)
    // A: 128 rows x 128 bytes = 1024 cp16
    #pragma unroll
    for (int i = 0; i < 4; i++) {
        int t = tid + i*256, r = t >> 3, ch = t & 7;
        cp16(sa + r*ASTR + ch*16, gA + (size_t)r*HB + k0 + ch*16);
    }
    // B: 256 rows x 128 bytes = 2048 cp16
    uint32_t sb = sa + A_ST;
    #pragma unroll
    for (int i = 0; i < 8; i++) {
        int t = tid + i*256, r = t >> 3, ch = t & 7;
        cp16(sb + r*ASTR + ch*16, gB + (size_t)r*HB + k0 + ch*16);
    }
}

__global__ __launch_bounds__(256, 1) void gemm_lse_kernel() {
    extern __shared__ __align__(128) char smem[];
    const int tid  = threadIdx.x;
    const int lane = tid & 31;
    const int w    = tid >> 5;
    const int wm   = w >> 2;      // 0..1
    const int wn   = w & 3;       // 0..3
    const int mt   = blockIdx.x;  // 0..15
    const int bt   = blockIdx.y;  // 0..593
    const uint32_t sbase = smem_u32(smem);

    const signed char* gA = g_Aq + (size_t)mt*BM*HB;
    const signed char* gB = g_Wq + (size_t)bt*BN*HB;

    int acc[4][8][4];
    #pragma unroll
    for (int i = 0; i < 4; i++)
        #pragma unroll
        for (int j = 0; j < 8; j++)
            #pragma unroll
            for (int q = 0; q < 4; q++) acc[i][j][q] = 0;

    // ldmatrix per-lane byte offsets (each "b16" = 2 int8)
    uint32_t aoff[4], boff[4];
    {
        int rowA = wm*64 + ((lane >> 3) & 1)*8 + (lane & 7);
        int colA = (lane >> 4)*16;            // bytes
        #pragma unroll
        for (int i = 0; i < 4; i++) aoff[i] = (uint32_t)((rowA + i*16)*ASTR + colA);
        int mm = lane >> 3, j2 = mm >> 1, cs = mm & 1;
        int rowB = wn*64 + j2*8 + (lane & 7);
        #pragma unroll
        for (int jj = 0; jj < 4; jj++)
            boff[jj] = (uint32_t)(A_ST + (rowB + jj*16)*ASTR + cs*16);
    }

    load_stage(sbase, 0, 0, gA, gB, tid); cp_commit();
    load_stage(sbase, 1, 1, gA, gB, tid); cp_commit();

    int s = 0;
    for (int c = 0; c < NCH; c++) {
        cp_wait1();
        __syncthreads();
        uint32_t sa = sbase + s*STG;
        #pragma unroll
        for (int ks = 0; ks < 4; ks++) {
            uint32_t kb = ks*32;              // 32 int8 = 32 bytes
            uint32_t af[4][4], bf[4][4];
            #pragma unroll
            for (int i = 0; i < 4; i++) ldmx4(af[i], sa + aoff[i] + kb);
            #pragma unroll
            for (int jj = 0; jj < 4; jj++) ldmx4(bf[jj], sa + boff[jj] + kb);
            #pragma unroll
            for (int i = 0; i < 4; i++)
                #pragma unroll
                for (int j = 0; j < 8; j++)
                    mma_s8(acc[i][j], af[i], bf[j >> 1][(j & 1)*2], bf[j >> 1][(j & 1)*2 + 1]);
        }
        if (c + 2 < NCH) {
            int sn = s + 2; if (sn >= NSTAGE) sn -= NSTAGE;
            load_stage(sbase, sn, c + 2, gA, gB, tid);
        }
        cp_commit();
        if (++s == NSTAGE) s = 0;
    }
    __syncthreads();

    // dequantize to float logits
    float fac[4][8][4];
    #pragma unroll
    for (int i = 0; i < 4; i++)
        #pragma unroll
        for (int j = 0; j < 8; j++)
            #pragma unroll
            for (int q = 0; q < 4; q++) fac[i][j][q] = (float)acc[i][j][q] * INV;

    // ---- epilogue: per-row max + sumexp over this CTA's 256 columns ----
    const bool dead = (bt == NT2 - 1) && (wn >= 2);   // ragged tail mask
    float* redM = (float*)smem;          // [128][4]
    float* redS = redM + 512;            // [128][4]

    #pragma unroll
    for (int i = 0; i < 4; i++) {
        float mx0 = -INFINITY, mx1 = -INFINITY;
        #pragma unroll
        for (int j = 0; j < 8; j++) {
            mx0 = fmaxf(mx0, fmaxf(fac[i][j][0], fac[i][j][1]));
            mx1 = fmaxf(mx1, fmaxf(fac[i][j][2], fac[i][j][3]));
        }
        #pragma unroll
        for (int o = 1; o < 4; o <<= 1) {
            mx0 = fmaxf(mx0, __shfl_xor_sync(0xffffffffu, mx0, o));
            mx1 = fmaxf(mx1, __shfl_xor_sync(0xffffffffu, mx1, o));
        }
        float s0 = 0.f, s1 = 0.f;
        #pragma unroll
        for (int j = 0; j < 8; j++) {
            s0 += __expf(fac[i][j][0] - mx0) + __expf(fac[i][j][1] - mx0);
            s1 += __expf(fac[i][j][2] - mx1) + __expf(fac[i][j][3] - mx1);
        }
        #pragma unroll
        for (int o = 1; o < 4; o <<= 1) {
            s0 += __shfl_xor_sync(0xffffffffu, s0, o);
            s1 += __shfl_xor_sync(0xffffffffu, s1, o);
        }
        if (dead) { mx0 = -INFINITY; mx1 = -INFINITY; s0 = 0.f; s1 = 0.f; }
        if ((lane & 3) == 0) {
            int r = wm*64 + i*16 + (lane >> 2);
            redM[r*4 + wn]     = mx0;  redS[r*4 + wn]     = s0;
            redM[(r+8)*4 + wn] = mx1;  redS[(r+8)*4 + wn] = s1;
        }
    }
    __syncthreads();

    if (tid < 128) {
        float m = redM[tid*4 + 0];
        #pragma unroll
        for (int t = 1; t < 4; t++) m = fmaxf(m, redM[tid*4 + t]);
        float sv = 0.f;
        #pragma unroll
        for (int t = 0; t < 4; t++) {
            float pm = redM[tid*4 + t];
            if (pm > -INFINITY) sv += redS[tid*4 + t] * __expf(pm - m);
        }
        size_t idx = (size_t)bt * M_ + (mt*128 + tid);
        g_pmax[idx] = m;
        g_psum[idx] = sv;
    }
}

// ---------------- exact fp32 label logits ------------------------------------
__global__ void labeldot_kernel(const float* __restrict__ hs,
                                const float* __restrict__ Wlm,
                                const int*   __restrict__ ids) {
    int b = blockIdx.x;
    int g = b / (S_-1), t = b % (S_-1);
    int m = g*S_ + t;
    int label = ids[g*S_ + t + 1];
    const float4* h4 = (const float4*)(hs  + (size_t)m*H_);
    const float4* w4 = (const float4*)(Wlm + (size_t)label*H_);
    float p = 0.f;
    for (int i = threadIdx.x; i < H_/4; i += 256) {
        float4 a = h4[i], bb = w4[i];
        p += a.x*bb.x + a.y*bb.y + a.z*bb.z + a.w*bb.w;
    }
    __shared__ float red[256];
    red[threadIdx.x] = p; __syncthreads();
    for (int s = 128; s > 0; s >>= 1) {
        if (threadIdx.x < s) red[threadIdx.x] += red[threadIdx.x + s];
        __syncthreads();
    }
    if (threadIdx.x == 0) g_labeldot[b] = red[0];
}

// ---------------- combine partials -> logsumexp -> token loss ----------------
__global__ void lse_kernel(const float* __restrict__ amask) {
    int b = blockIdx.x;
    int g = b / (S_-1), t = b % (S_-1);
    int m = g*S_ + t;

    float mx = -INFINITY, sm = 0.f;
    for (int nt = threadIdx.x; nt < NT2; nt += 256) {
        float pm = g_pmax[(size_t)nt*M_ + m];
        float ps = g_psum[(size_t)nt*M_ + m];
        if (pm > mx) { sm = sm*__expf(mx - pm) + ps; mx = pm; }
        else         { sm += ps*__expf(pm - mx); }
    }
    __shared__ float rm[256], rs[256];
    rm[threadIdx.x] = mx; rs[threadIdx.x] = sm;
    __syncthreads();
    for (int s = 128; s > 0; s >>= 1) {
        if (threadIdx.x < s) {
            float m1 = rm[threadIdx.x],     s1 = rs[threadIdx.x];
            float m2 = rm[threadIdx.x + s], s2 = rs[threadIdx.x + s];
            float M  = fmaxf(m1, m2);
            rm[threadIdx.x] = M;
            rs[threadIdx.x] = s1*__expf(m1 - M) + s2*__expf(m2 - M);
        }
        __syncthreads();
    }
    if (threadIdx.x == 0) {
        float lse = rm[0] + logf(rs[0]);
        g_tokloss[b] = (lse - g_labeldot[b]) * amask[g*S_ + t + 1];
    }
}

// ---------------- final weighted mean ----------------------------------------
__global__ void final_kernel(const float* __restrict__ amask,
                             const float* __restrict__ adv,
                             float* __restrict__ out) {
    __shared__ float sl[512], sk[512];
    int tid = threadIdx.x;
    int g = tid >> 7, idx = tid & 127;
    float pl = 0.f, pm = 0.f;
    for (int j = idx; j < S_-1; j += 128) {
        pl += g_tokloss[g*(S_-1) + j];
        pm += amask[g*S_ + 1 + j];
    }
    sl[tid] = pl; sk[tid] = pm;
    __syncthreads();
    for (int s = 64; s > 0; s >>= 1) {
        if (idx < s) { sl[tid] += sl[tid + s]; sk[tid] += sk[tid + s]; }
        __syncthreads();
    }
    if (tid == 0) {
        float acc = 0.f;
        for (int gg = 0; gg < G_; gg++) {
            float len = fmaxf(sk[gg*128], 1.0f);
            acc += (sl[gg*128] / len) * adv[gg];
        }
        out[0] = acc / (float)G_;
    }
}

// ---------------- launch ------------------------------------------------------
// Order chosen so the gemm is our 4th launch: with the harness's ~2 internal
// launches ahead, ncu's "-s 5 -c 1" lands on the gemm.
extern "C" void kernel_launch(void* const* d_in, const int* in_sizes, int n_in,
                              void* d_out, int out_size) {
    const float* hs    = (const float*)d_in[0];
    const float* Wlm   = (const float*)d_in[1];
    const int*   ids   = (const int*)  d_in[2];
    const float* amask = (const float*)d_in[3];
    const float* adv   = (const float*)d_in[4];
    float* out = (float*)d_out;

    cudaFuncSetAttribute(gemm_lse_kernel,
                         cudaFuncAttributeMaxDynamicSharedMemorySize,
                         NSTAGE*STG);

    labeldot_kernel<<<TOKS, 256>>>(hs, Wlm, ids);          // 1
    convA_kernel<<<(M_*(H_/8) + 255)/256, 256>>>(hs);      // 2
    convW_kernel<<<4096, 256>>>(Wlm);                      // 3

    dim3 grid(M_/BM, NT2);               // x = m-tile fast -> B reused via L2
    gemm_lse_kernel<<<grid, 256, NSTAGE*STG>>>();          // 4  <- ncu target

    lse_kernel<<<TOKS, 256>>>(amask);                      // 5
    final_kernel<<<1, 512>>>(amask, adv, out);             // 6
}

// round 9
// speedup vs baseline: 2.6134x; 2.6134x over previous
#include <cuda_runtime.h>
#include <cuda_fp16.h>
#include <math.h>
#include <stdint.h>

// Problem constants
#define G_  4
#define S_  512
#define H_  2048
#define V_  151936
#define M_  (G_*S_)              // 2048
#define TOKS (G_*(S_-1))         // 2044
#define NT2 594                  // ceil(V/256) n-tiles of 256 (last is ragged)

// GEMM tiling (fp16: K-chunk = 64 elements = 128 bytes/row)
#define BM 128
#define BN 256
#define KT 64
#define NCH (H_/KT)              // 32 k-chunks
#define ASTR 144                 // smem bytes per row (pad, conflict-free)
#define A_ST (BM*ASTR)           // 18432
#define B_ST (BN*ASTR)           // 36864
#define STG  (A_ST+B_ST)         // 55296 per stage
#define NSTAGE 3                 // 165888 B dynamic smem

// ---------------- scratch (no allocs -> __device__ globals) ------------------
__device__ __half g_Whf[(size_t)(V_+128)*H_];   // fp16 W, zero-padded tail rows
__device__ __half g_Ahf[(size_t)M_*H_];         // fp16 hidden
__device__ float g_pmax[(size_t)NT2*M_];
__device__ float g_psum[(size_t)NT2*M_];
__device__ float g_labeldot[TOKS];
__device__ float g_tokloss[TOKS];

// ---------------- helpers ----------------------------------------------------
__device__ __forceinline__ uint32_t smem_u32(const void* p) {
    uint32_t a;
    asm("{ .reg .u64 t; cvta.to.shared.u64 t, %1; cvt.u32.u64 %0, t; }" : "=r"(a) : "l"(p));
    return a;
}
__device__ __forceinline__ void cp16(uint32_t dst, const void* src) {
    asm volatile("cp.async.cg.shared.global [%0], [%1], 16;"
                 :: "r"(dst), "l"(__cvta_generic_to_global(src)) : "memory");
}
__device__ __forceinline__ void cp_commit() {
    asm volatile("cp.async.commit_group;" ::: "memory");
}
__device__ __forceinline__ void cp_wait1() {
    asm volatile("cp.async.wait_group 1;" ::: "memory");
}
__device__ __forceinline__ void ldmx4(uint32_t* r, uint32_t addr) {
    asm volatile("ldmatrix.sync.aligned.m8n8.x4.shared.b16 {%0,%1,%2,%3}, [%4];"
                 : "=r"(r[0]), "=r"(r[1]), "=r"(r[2]), "=r"(r[3]) : "r"(addr));
}
// fp16 inputs, fp16 accumulate: D(2x f16x2) = A(4) * B(2) + C(2x f16x2)
__device__ __forceinline__ void mma_h(uint32_t* d, const uint32_t* a, uint32_t b0, uint32_t b1) {
    asm volatile(
        "mma.sync.aligned.m16n8k16.row.col.f16.f16.f16.f16 "
        "{%0,%1}, {%2,%3,%4,%5}, {%6,%7}, {%0,%1};"
        : "+r"(d[0]), "+r"(d[1])
        : "r"(a[0]), "r"(a[1]), "r"(a[2]), "r"(a[3]), "r"(b0), "r"(b1));
}

// ---------------- fp32 -> fp16 conversion ------------------------------------
__global__ void convW_kernel(const float* __restrict__ src) {
    size_t n8 = (size_t)V_*(H_/8);
    size_t stride = (size_t)gridDim.x*blockDim.x;
    const float4* s4 = (const float4*)src;
    uint4* d4 = (uint4*)g_Whf;
    for (size_t i = (size_t)blockIdx.x*blockDim.x + threadIdx.x; i < n8; i += stride) {
        float4 f0 = s4[2*i], f1 = s4[2*i+1];
        __half2 h0 = __float22half2_rn(make_float2(f0.x, f0.y));
        __half2 h1 = __float22half2_rn(make_float2(f0.z, f0.w));
        __half2 h2 = __float22half2_rn(make_float2(f1.x, f1.y));
        __half2 h3 = __float22half2_rn(make_float2(f1.z, f1.w));
        uint4 u;
        u.x = *(unsigned*)&h0; u.y = *(unsigned*)&h1;
        u.z = *(unsigned*)&h2; u.w = *(unsigned*)&h3;
        d4[i] = u;
    }
}
__global__ void convA_kernel(const float* __restrict__ src) {
    size_t i = (size_t)blockIdx.x*blockDim.x + threadIdx.x;
    size_t n8 = (size_t)M_*(H_/8);
    if (i >= n8) return;
    const float4* s4 = (const float4*)src;
    float4 f0 = s4[2*i], f1 = s4[2*i+1];
    __half2 h0 = __float22half2_rn(make_float2(f0.x, f0.y));
    __half2 h1 = __float22half2_rn(make_float2(f0.z, f0.w));
    __half2 h2 = __float22half2_rn(make_float2(f1.x, f1.y));
    __half2 h3 = __float22half2_rn(make_float2(f1.z, f1.w));
    uint4 u;
    u.x = *(unsigned*)&h0; u.y = *(unsigned*)&h1;
    u.z = *(unsigned*)&h2; u.w = *(unsigned*)&h3;
    ((uint4*)g_Ahf)[i] = u;
}

// ---------------- GEMM (128x256 fp16, fp16 accum) + online softmax partials --
// 256 threads, 8 warps (2x4), warp tile 64x64, cp.async 3-stage pipeline.
__device__ __forceinline__ void load_stage(uint32_t sbase, int s, int c,
                                           const __half* gA,
                                           const __half* gB, int tid) {
    uint32_t sa = sbase + s*STG;
    int k0 = c*KT;
    // A: 128 rows x 128 bytes = 1024 cp16
    #pragma unroll
    for (int i = 0; i < 4; i++) {
        int t = tid + i*256, r = t >> 3, ch = t & 7;
        cp16(sa + r*ASTR + ch*16, gA + (size_t)r*H_ + k0 + ch*8);
    }
    // B: 256 rows x 128 bytes = 2048 cp16
    uint32_t sb = sa + A_ST;
    #pragma unroll
    for (int i = 0; i < 8; i++) {
        int t = tid + i*256, r = t >> 3, ch = t & 7;
        cp16(sb + r*ASTR + ch*16, gB + (size_t)r*H_ + k0 + ch*8);
    }
}

__global__ __launch_bounds__(256, 1) void gemm_lse_kernel() {
    extern __shared__ __align__(128) char smem[];
    const int tid  = threadIdx.x;
    const int lane = tid & 31;
    const int w    = tid >> 5;
    const int wm   = w >> 2;      // 0..1
    const int wn   = w & 3;       // 0..3
    const int mt   = blockIdx.x;  // 0..15
    const int bt   = blockIdx.y;  // 0..593
    const uint32_t sbase = smem_u32(smem);

    const __half* gA = g_Ahf + (size_t)mt*BM*H_;
    const __half* gB = g_Whf + (size_t)bt*BN*H_;

    uint32_t acc[4][8][2];        // fp16x2 pairs: [0]=(c0,c1)@row r, [1]=(c2,c3)@row r+8
    #pragma unroll
    for (int i = 0; i < 4; i++)
        #pragma unroll
        for (int j = 0; j < 8; j++) { acc[i][j][0] = 0u; acc[i][j][1] = 0u; }

    // ldmatrix per-lane byte offsets
    uint32_t aoff[4], boff[4];
    {
        int rowA = wm*64 + ((lane >> 3) & 1)*8 + (lane & 7);
        int colA = (lane >> 4)*16;            // bytes (8 fp16)
        #pragma unroll
        for (int i = 0; i < 4; i++) aoff[i] = (uint32_t)((rowA + i*16)*ASTR + colA);
        int mm = lane >> 3, j2 = mm >> 1, cs = mm & 1;
        int rowB = wn*64 + j2*8 + (lane & 7);
        #pragma unroll
        for (int jj = 0; jj < 4; jj++)
            boff[jj] = (uint32_t)(A_ST + (rowB + jj*16)*ASTR + cs*16);
    }

    load_stage(sbase, 0, 0, gA, gB, tid); cp_commit();
    load_stage(sbase, 1, 1, gA, gB, tid); cp_commit();

    int s = 0;
    for (int c = 0; c < NCH; c++) {
        cp_wait1();
        __syncthreads();
        uint32_t sa = sbase + s*STG;
        #pragma unroll
        for (int ks = 0; ks < 4; ks++) {
            uint32_t kb = ks*32;              // 16 fp16 = 32 bytes
            uint32_t af[4][4], bf[4][4];
            #pragma unroll
            for (int i = 0; i < 4; i++) ldmx4(af[i], sa + aoff[i] + kb);
            #pragma unroll
            for (int jj = 0; jj < 4; jj++) ldmx4(bf[jj], sa + boff[jj] + kb);
            #pragma unroll
            for (int i = 0; i < 4; i++)
                #pragma unroll
                for (int j = 0; j < 8; j++)
                    mma_h(acc[i][j], af[i], bf[j >> 1][(j & 1)*2], bf[j >> 1][(j & 1)*2 + 1]);
        }
        if (c + 2 < NCH) {
            int sn = s + 2; if (sn >= NSTAGE) sn -= NSTAGE;
            load_stage(sbase, sn, c + 2, gA, gB, tid);
        }
        cp_commit();
        if (++s == NSTAGE) s = 0;
    }
    __syncthreads();

    // ---- epilogue: per-row max + sumexp over this CTA's 256 columns ----
    const bool dead = (bt == NT2 - 1) && (wn >= 2);   // ragged tail mask
    float* redM = (float*)smem;          // [128][4]
    float* redS = redM + 512;            // [128][4]

    #pragma unroll
    for (int i = 0; i < 4; i++) {
        // unpack fp16 accumulators to float
        float v0[16], v1[16];
        #pragma unroll
        for (int j = 0; j < 8; j++) {
            float2 p0 = __half22float2(*(const __half2*)&acc[i][j][0]);
            float2 p1 = __half22float2(*(const __half2*)&acc[i][j][1]);
            v0[2*j] = p0.x; v0[2*j+1] = p0.y;
            v1[2*j] = p1.x; v1[2*j+1] = p1.y;
        }
        float mx0 = -INFINITY, mx1 = -INFINITY;
        #pragma unroll
        for (int q = 0; q < 16; q++) {
            mx0 = fmaxf(mx0, v0[q]);
            mx1 = fmaxf(mx1, v1[q]);
        }
        #pragma unroll
        for (int o = 1; o < 4; o <<= 1) {
            mx0 = fmaxf(mx0, __shfl_xor_sync(0xffffffffu, mx0, o));
            mx1 = fmaxf(mx1, __shfl_xor_sync(0xffffffffu, mx1, o));
        }
        float s0 = 0.f, s1 = 0.f;
        #pragma unroll
        for (int q = 0; q < 16; q++) {
            s0 += __expf(v0[q] - mx0);
            s1 += __expf(v1[q] - mx1);
        }
        #pragma unroll
        for (int o = 1; o < 4; o <<= 1) {
            s0 += __shfl_xor_sync(0xffffffffu, s0, o);
            s1 += __shfl_xor_sync(0xffffffffu, s1, o);
        }
        if (dead) { mx0 = -INFINITY; mx1 = -INFINITY; s0 = 0.f; s1 = 0.f; }
        if ((lane & 3) == 0) {
            int r = wm*64 + i*16 + (lane >> 2);
            redM[r*4 + wn]     = mx0;  redS[r*4 + wn]     = s0;
            redM[(r+8)*4 + wn] = mx1;  redS[(r+8)*4 + wn] = s1;
        }
    }
    __syncthreads();

    if (tid < 128) {
        float m = redM[tid*4 + 0];
        #pragma unroll
        for (int t = 1; t < 4; t++) m = fmaxf(m, redM[tid*4 + t]);
        float sv = 0.f;
        #pragma unroll
        for (int t = 0; t < 4; t++) {
            float pm = redM[tid*4 + t];
            if (pm > -INFINITY) sv += redS[tid*4 + t] * __expf(pm - m);
        }
        size_t idx = (size_t)bt * M_ + (mt*128 + tid);
        g_pmax[idx] = m;
        g_psum[idx] = sv;
    }
}

// ---------------- exact fp32 label logits ------------------------------------
__global__ void labeldot_kernel(const float* __restrict__ hs,
                                const float* __restrict__ Wlm,
                                const int*   __restrict__ ids) {
    int b = blockIdx.x;
    int g = b / (S_-1), t = b % (S_-1);
    int m = g*S_ + t;
    int label = ids[g*S_ + t + 1];
    const float4* h4 = (const float4*)(hs  + (size_t)m*H_);
    const float4* w4 = (const float4*)(Wlm + (size_t)label*H_);
    float p = 0.f;
    for (int i = threadIdx.x; i < H_/4; i += 256) {
        float4 a = h4[i], bb = w4[i];
        p += a.x*bb.x + a.y*bb.y + a.z*bb.z + a.w*bb.w;
    }
    __shared__ float red[256];
    red[threadIdx.x] = p; __syncthreads();
    for (int s = 128; s > 0; s >>= 1) {
        if (threadIdx.x < s) red[threadIdx.x] += red[threadIdx.x + s];
        __syncthreads();
    }
    if (threadIdx.x == 0) g_labeldot[b] = red[0];
}

// ---------------- combine partials -> logsumexp -> token loss ----------------
__global__ void lse_kernel(const float* __restrict__ amask) {
    int b = blockIdx.x;
    int g = b / (S_-1), t = b % (S_-1);
    int m = g*S_ + t;

    float mx = -INFINITY, sm = 0.f;
    for (int nt = threadIdx.x; nt < NT2; nt += 256) {
        float pm = g_pmax[(size_t)nt*M_ + m];
        float ps = g_psum[(size_t)nt*M_ + m];
        if (pm > mx) { sm = sm*__expf(mx - pm) + ps; mx = pm; }
        else         { sm += ps*__expf(pm - mx); }
    }
    __shared__ float rm[256], rs[256];
    rm[threadIdx.x] = mx; rs[threadIdx.x] = sm;
    __syncthreads();
    for (int s = 128; s > 0; s >>= 1) {
        if (threadIdx.x < s) {
            float m1 = rm[threadIdx.x],     s1 = rs[threadIdx.x];
            float m2 = rm[threadIdx.x + s], s2 = rs[threadIdx.x + s];
            float M  = fmaxf(m1, m2);
            rm[threadIdx.x] = M;
            rs[threadIdx.x] = s1*__expf(m1 - M) + s2*__expf(m2 - M);
        }
        __syncthreads();
    }
    if (threadIdx.x == 0) {
        float lse = rm[0] + logf(rs[0]);
        g_tokloss[b] = (lse - g_labeldot[b]) * amask[g*S_ + t + 1];
    }
}

// ---------------- final weighted mean ----------------------------------------
__global__ void final_kernel(const float* __restrict__ amask,
                             const float* __restrict__ adv,
                             float* __restrict__ out) {
    __shared__ float sl[512], sk[512];
    int tid = threadIdx.x;
    int g = tid >> 7, idx = tid & 127;
    float pl = 0.f, pm = 0.f;
    for (int j = idx; j < S_-1; j += 128) {
        pl += g_tokloss[g*(S_-1) + j];
        pm += amask[g*S_ + 1 + j];
    }
    sl[tid] = pl; sk[tid] = pm;
    __syncthreads();
    for (int s = 64; s > 0; s >>= 1) {
        if (idx < s) { sl[tid] += sl[tid + s]; sk[tid] += sk[tid + s]; }
        __syncthreads();
    }
    if (tid == 0) {
        float acc = 0.f;
        for (int gg = 0; gg < G_; gg++) {
            float len = fmaxf(sk[gg*128], 1.0f);
            acc += (sl[gg*128] / len) * adv[gg];
        }
        out[0] = acc / (float)G_;
    }
}

// ---------------- launch ------------------------------------------------------
// Gemm is our 4th launch so ncu's "-s 5 -c 1" lands on it.
extern "C" void kernel_launch(void* const* d_in, const int* in_sizes, int n_in,
                              void* d_out, int out_size) {
    const float* hs    = (const float*)d_in[0];
    const float* Wlm   = (const float*)d_in[1];
    const int*   ids   = (const int*)  d_in[2];
    const float* amask = (const float*)d_in[3];
    const float* adv   = (const float*)d_in[4];
    float* out = (float*)d_out;

    cudaFuncSetAttribute(gemm_lse_kernel,
                         cudaFuncAttributeMaxDynamicSharedMemorySize,
                         NSTAGE*STG);

    labeldot_kernel<<<TOKS, 256>>>(hs, Wlm, ids);          // 1
    convA_kernel<<<(M_*(H_/8) + 255)/256, 256>>>(hs);      // 2
    convW_kernel<<<4096, 256>>>(Wlm);                      // 3

    dim3 grid(M_/BM, NT2);               // x = m-tile fast -> B reused via L2
    gemm_lse_kernel<<<grid, 256, NSTAGE*STG>>>();          // 4  <- ncu target

    lse_kernel<<<TOKS, 256>>>(amask);                      // 5
    final_kernel<<<1, 512>>>(amask, adv, out);             // 6
}

// round 11
// speedup vs baseline: 2.6224x; 1.0034x over previous
#include <cuda_runtime.h>
#include <cuda_fp16.h>
#include <math.h>
#include <stdint.h>

// Problem constants
#define G_  4
#define S_  512
#define H_  2048
#define V_  151936
#define M_  (G_*S_)              // 2048
#define TOKS (G_*(S_-1))         // 2044
#define NT2 594                  // ceil(V/256) n-tiles of 256 (last is ragged)

// GEMM tiling (fp16: K-chunk = 64 elements = 128 bytes/row)
#define BM 128
#define BN 256
#define KT 64
#define NCH (H_/KT)              // 32 k-chunks
#define ASTR 144                 // smem bytes per row (pad, conflict-free)
#define A_ST (BM*ASTR)           // 18432
#define B_ST (BN*ASTR)           // 36864
#define STG  (A_ST+B_ST)         // 55296 per stage
#define NSTAGE 3                 // 165888 B dynamic smem
#define NTHR 512                 // 16 warps: 4x4 warp grid, warp tile 32x64

// ---------------- scratch (no allocs -> __device__ globals) ------------------
__device__ __half g_Whf[(size_t)(V_+128)*H_];   // fp16 W, zero-padded tail rows
__device__ __half g_Ahf[(size_t)M_*H_];         // fp16 hidden
__device__ float g_pmax[(size_t)NT2*M_];
__device__ float g_psum[(size_t)NT2*M_];
__device__ float g_labeldot[TOKS];
__device__ float g_tokloss[TOKS];

// ---------------- helpers ----------------------------------------------------
__device__ __forceinline__ uint32_t smem_u32(const void* p) {
    uint32_t a;
    asm("{ .reg .u64 t; cvta.to.shared.u64 t, %1; cvt.u32.u64 %0, t; }" : "=r"(a) : "l"(p));
    return a;
}
__device__ __forceinline__ void cp16(uint32_t dst, const void* src) {
    asm volatile("cp.async.cg.shared.global [%0], [%1], 16;"
                 :: "r"(dst), "l"(__cvta_generic_to_global(src)) : "memory");
}
__device__ __forceinline__ void cp_commit() {
    asm volatile("cp.async.commit_group;" ::: "memory");
}
__device__ __forceinline__ void cp_wait1() {
    asm volatile("cp.async.wait_group 1;" ::: "memory");
}
__device__ __forceinline__ void ldmx4(uint32_t* r, uint32_t addr) {
    asm volatile("ldmatrix.sync.aligned.m8n8.x4.shared.b16 {%0,%1,%2,%3}, [%4];"
                 : "=r"(r[0]), "=r"(r[1]), "=r"(r[2]), "=r"(r[3]) : "r"(addr));
}
// fp16 inputs, fp16 accumulate
__device__ __forceinline__ void mma_h(uint32_t* d, const uint32_t* a, uint32_t b0, uint32_t b1) {
    asm volatile(
        "mma.sync.aligned.m16n8k16.row.col.f16.f16.f16.f16 "
        "{%0,%1}, {%2,%3,%4,%5}, {%6,%7}, {%0,%1};"
        : "+r"(d[0]), "+r"(d[1])
        : "r"(a[0]), "r"(a[1]), "r"(a[2]), "r"(a[3]), "r"(b0), "r"(b1));
}

// ---------------- fp32 -> fp16 conversion ------------------------------------
__global__ void convW_kernel(const float* __restrict__ src) {
    size_t n8 = (size_t)V_*(H_/8);
    size_t stride = (size_t)gridDim.x*blockDim.x;
    const float4* s4 = (const float4*)src;
    uint4* d4 = (uint4*)g_Whf;
    for (size_t i = (size_t)blockIdx.x*blockDim.x + threadIdx.x; i < n8; i += stride) {
        float4 f0 = s4[2*i], f1 = s4[2*i+1];
        __half2 h0 = __float22half2_rn(make_float2(f0.x, f0.y));
        __half2 h1 = __float22half2_rn(make_float2(f0.z, f0.w));
        __half2 h2 = __float22half2_rn(make_float2(f1.x, f1.y));
        __half2 h3 = __float22half2_rn(make_float2(f1.z, f1.w));
        uint4 u;
        u.x = *(unsigned*)&h0; u.y = *(unsigned*)&h1;
        u.z = *(unsigned*)&h2; u.w = *(unsigned*)&h3;
        d4[i] = u;
    }
}
__global__ void convA_kernel(const float* __restrict__ src) {
    size_t i = (size_t)blockIdx.x*blockDim.x + threadIdx.x;
    size_t n8 = (size_t)M_*(H_/8);
    if (i >= n8) return;
    const float4* s4 = (const float4*)src;
    float4 f0 = s4[2*i], f1 = s4[2*i+1];
    __half2 h0 = __float22half2_rn(make_float2(f0.x, f0.y));
    __half2 h1 = __float22half2_rn(make_float2(f0.z, f0.w));
    __half2 h2 = __float22half2_rn(make_float2(f1.x, f1.y));
    __half2 h3 = __float22half2_rn(make_float2(f1.z, f1.w));
    uint4 u;
    u.x = *(unsigned*)&h0; u.y = *(unsigned*)&h1;
    u.z = *(unsigned*)&h2; u.w = *(unsigned*)&h3;
    ((uint4*)g_Ahf)[i] = u;
}

// ---------------- GEMM (128x256 fp16/f16) + online softmax partials ----------
// 512 threads, 16 warps (4x4), warp tile 32x64, cp.async 3-stage pipeline.
__device__ __forceinline__ void load_stage(uint32_t sbase, int s, int c,
                                           const __half* gA,
                                           const __half* gB, int tid) {
    uint32_t sa = sbase + s*STG;
    int k0 = c*KT;
    // A: 128 rows x 128 bytes = 1024 cp16
    #pragma unroll
    for (int i = 0; i < 2; i++) {
        int t = tid + i*NTHR, r = t >> 3, ch = t & 7;
        cp16(sa + r*ASTR + ch*16, gA + (size_t)r*H_ + k0 + ch*8);
    }
    // B: 256 rows x 128 bytes = 2048 cp16
    uint32_t sb = sa + A_ST;
    #pragma unroll
    for (int i = 0; i < 4; i++) {
        int t = tid + i*NTHR, r = t >> 3, ch = t & 7;
        cp16(sb + r*ASTR + ch*16, gB + (size_t)r*H_ + k0 + ch*8);
    }
}

__global__ __launch_bounds__(NTHR, 1) void gemm_lse_kernel() {
    extern __shared__ __align__(128) char smem[];
    const int tid  = threadIdx.x;
    const int lane = tid & 31;
    const int w    = tid >> 5;
    const int wm   = w >> 2;      // 0..3 (32-row slices)
    const int wn   = w & 3;       // 0..3 (64-col slices)
    const int mt   = blockIdx.x;  // 0..15
    const int bt   = blockIdx.y;  // 0..593
    const uint32_t sbase = smem_u32(smem);

    const __half* gA = g_Ahf + (size_t)mt*BM*H_;
    const __half* gB = g_Whf + (size_t)bt*BN*H_;

    uint32_t acc[2][8][2];        // fp16x2 pairs: [0]=(c0,c1)@row r, [1]=(c2,c3)@row r+8
    #pragma unroll
    for (int i = 0; i < 2; i++)
        #pragma unroll
        for (int j = 0; j < 8; j++) { acc[i][j][0] = 0u; acc[i][j][1] = 0u; }

    // ldmatrix per-lane byte offsets
    uint32_t aoff[2], boff[4];
    {
        int rowA = wm*32 + ((lane >> 3) & 1)*8 + (lane & 7);
        int colA = (lane >> 4)*16;            // bytes (8 fp16)
        #pragma unroll
        for (int i = 0; i < 2; i++) aoff[i] = (uint32_t)((rowA + i*16)*ASTR + colA);
        int mm = lane >> 3, j2 = mm >> 1, cs = mm & 1;
        int rowB = wn*64 + j2*8 + (lane & 7);
        #pragma unroll
        for (int jj = 0; jj < 4; jj++)
            boff[jj] = (uint32_t)(A_ST + (rowB + jj*16)*ASTR + cs*16);
    }

    load_stage(sbase, 0, 0, gA, gB, tid); cp_commit();
    load_stage(sbase, 1, 1, gA, gB, tid); cp_commit();

    int s = 0;
    for (int c = 0; c < NCH; c++) {
        cp_wait1();
        __syncthreads();
        uint32_t sa = sbase + s*STG;
        #pragma unroll
        for (int ks = 0; ks < 4; ks++) {
            uint32_t kb = ks*32;              // 16 fp16 = 32 bytes
            uint32_t af[2][4], bf[4][4];
            #pragma unroll
            for (int i = 0; i < 2; i++) ldmx4(af[i], sa + aoff[i] + kb);
            #pragma unroll
            for (int jj = 0; jj < 4; jj++) ldmx4(bf[jj], sa + boff[jj] + kb);
            #pragma unroll
            for (int i = 0; i < 2; i++)
                #pragma unroll
                for (int j = 0; j < 8; j++)
                    mma_h(acc[i][j], af[i], bf[j >> 1][(j & 1)*2], bf[j >> 1][(j & 1)*2 + 1]);
        }
        if (c + 2 < NCH) {
            int sn = s + 2; if (sn >= NSTAGE) sn -= NSTAGE;
            load_stage(sbase, sn, c + 2, gA, gB, tid);
        }
        cp_commit();
        if (++s == NSTAGE) s = 0;
    }
    __syncthreads();

    // ---- epilogue: per-row max + sumexp over this CTA's 256 columns ----
    const bool dead = (bt == NT2 - 1) && (wn >= 2);   // ragged tail mask
    float* redM = (float*)smem;          // [128][4]
    float* redS = redM + 512;            // [128][4]

    #pragma unroll
    for (int i = 0; i < 2; i++) {
        float v0[16], v1[16];
        #pragma unroll
        for (int j = 0; j < 8; j++) {
            float2 p0 = __half22float2(*(const __half2*)&acc[i][j][0]);
            float2 p1 = __half22float2(*(const __half2*)&acc[i][j][1]);
            v0[2*j] = p0.x; v0[2*j+1] = p0.y;
            v1[2*j] = p1.x; v1[2*j+1] = p1.y;
        }
        float mx0 = -INFINITY, mx1 = -INFINITY;
        #pragma unroll
        for (int q = 0; q < 16; q++) {
            mx0 = fmaxf(mx0, v0[q]);
            mx1 = fmaxf(mx1, v1[q]);
        }
        #pragma unroll
        for (int o = 1; o < 4; o <<= 1) {
            mx0 = fmaxf(mx0, __shfl_xor_sync(0xffffffffu, mx0, o));
            mx1 = fmaxf(mx1, __shfl_xor_sync(0xffffffffu, mx1, o));
        }
        float s0 = 0.f, s1 = 0.f;
        #pragma unroll
        for (int q = 0; q < 16; q++) {
            s0 += __expf(v0[q] - mx0);
            s1 += __expf(v1[q] - mx1);
        }
        #pragma unroll
        for (int o = 1; o < 4; o <<= 1) {
            s0 += __shfl_xor_sync(0xffffffffu, s0, o);
            s1 += __shfl_xor_sync(0xffffffffu, s1, o);
        }
        if (dead) { mx0 = -INFINITY; mx1 = -INFINITY; s0 = 0.f; s1 = 0.f; }
        if ((lane & 3) == 0) {
            int r = wm*32 + i*16 + (lane >> 2);
            redM[r*4 + wn]     = mx0;  redS[r*4 + wn]     = s0;
            redM[(r+8)*4 + wn] = mx1;  redS[(r+8)*4 + wn] = s1;
        }
    }
    __syncthreads();

    if (tid < 128) {
        float m = redM[tid*4 + 0];
        #pragma unroll
        for (int t = 1; t < 4; t++) m = fmaxf(m, redM[tid*4 + t]);
        float sv = 0.f;
        #pragma unroll
        for (int t = 0; t < 4; t++) {
            float pm = redM[tid*4 + t];
            if (pm > -INFINITY) sv += redS[tid*4 + t] * __expf(pm - m);
        }
        size_t idx = (size_t)bt * M_ + (mt*128 + tid);
        g_pmax[idx] = m;
        g_psum[idx] = sv;
    }
}

// ---------------- exact fp32 label logits ------------------------------------
__global__ void labeldot_kernel(const float* __restrict__ hs,
                                const float* __restrict__ Wlm,
                                const int*   __restrict__ ids) {
    int b = blockIdx.x;
    int g = b / (S_-1), t = b % (S_-1);
    int m = g*S_ + t;
    int label = ids[g*S_ + t + 1];
    const float4* h4 = (const float4*)(hs  + (size_t)m*H_);
    const float4* w4 = (const float4*)(Wlm + (size_t)label*H_);
    float p = 0.f;
    for (int i = threadIdx.x; i < H_/4; i += 256) {
        float4 a = h4[i], bb = w4[i];
        p += a.x*bb.x + a.y*bb.y + a.z*bb.z + a.w*bb.w;
    }
    __shared__ float red[256];
    red[threadIdx.x] = p; __syncthreads();
    for (int s = 128; s > 0; s >>= 1) {
        if (threadIdx.x < s) red[threadIdx.x] += red[threadIdx.x + s];
        __syncthreads();
    }
    if (threadIdx.x == 0) g_labeldot[b] = red[0];
}

// ---------------- combine partials -> logsumexp -> token loss ----------------
__global__ void lse_kernel(const float* __restrict__ amask) {
    int b = blockIdx.x;
    int g = b / (S_-1), t = b % (S_-1);
    int m = g*S_ + t;

    float mx = -INFINITY, sm = 0.f;
    for (int nt = threadIdx.x; nt < NT2; nt += 256) {
        float pm = g_pmax[(size_t)nt*M_ + m];
        float ps = g_psum[(size_t)nt*M_ + m];
        if (pm > mx) { sm = sm*__expf(mx - pm) + ps; mx = pm; }
        else         { sm += ps*__expf(pm - mx); }
    }
    __shared__ float rm[256], rs[256];
    rm[threadIdx.x] = mx; rs[threadIdx.x] = sm;
    __syncthreads();
    for (int s = 128; s > 0; s >>= 1) {
        if (threadIdx.x < s) {
            float m1 = rm[threadIdx.x],     s1 = rs[threadIdx.x];
            float m2 = rm[threadIdx.x + s], s2 = rs[threadIdx.x + s];
            float M  = fmaxf(m1, m2);
            rm[threadIdx.x] = M;
            rs[threadIdx.x] = s1*__expf(m1 - M) + s2*__expf(m2 - M);
        }
        __syncthreads();
    }
    if (threadIdx.x == 0) {
        float lse = rm[0] + logf(rs[0]);
        g_tokloss[b] = (lse - g_labeldot[b]) * amask[g*S_ + t + 1];
    }
}

// ---------------- final weighted mean ----------------------------------------
__global__ void final_kernel(const float* __restrict__ amask,
                             const float* __restrict__ adv,
                             float* __restrict__ out) {
    __shared__ float sl[512], sk[512];
    int tid = threadIdx.x;
    int g = tid >> 7, idx = tid & 127;
    float pl = 0.f, pm = 0.f;
    for (int j = idx; j < S_-1; j += 128) {
        pl += g_tokloss[g*(S_-1) + j];
        pm += amask[g*S_ + 1 + j];
    }
    sl[tid] = pl; sk[tid] = pm;
    __syncthreads();
    for (int s = 64; s > 0; s >>= 1) {
        if (idx < s) { sl[tid] += sl[tid + s]; sk[tid] += sk[tid + s]; }
        __syncthreads();
    }
    if (tid == 0) {
        float acc = 0.f;
        for (int gg = 0; gg < G_; gg++) {
            float len = fmaxf(sk[gg*128], 1.0f);
            acc += (sl[gg*128] / len) * adv[gg];
        }
        out[0] = acc / (float)G_;
    }
}

// ---------------- launch ------------------------------------------------------
// Gemm is our 4th launch so ncu's "-s 5 -c 1" lands on it.
extern "C" void kernel_launch(void* const* d_in, const int* in_sizes, int n_in,
                              void* d_out, int out_size) {
    const float* hs    = (const float*)d_in[0];
    const float* Wlm   = (const float*)d_in[1];
    const int*   ids   = (const int*)  d_in[2];
    const float* amask = (const float*)d_in[3];
    const float* adv   = (const float*)d_in[4];
    float* out = (float*)d_out;

    cudaFuncSetAttribute(gemm_lse_kernel,
                         cudaFuncAttributeMaxDynamicSharedMemorySize,
                         NSTAGE*STG);

    labeldot_kernel<<<TOKS, 256>>>(hs, Wlm, ids);          // 1
    convA_kernel<<<(M_*(H_/8) + 255)/256, 256>>>(hs);      // 2
    convW_kernel<<<4096, 256>>>(Wlm);                      // 3

    dim3 grid(M_/BM, NT2);               // x = m-tile fast -> B reused via L2
    gemm_lse_kernel<<<grid, NTHR, NSTAGE*STG>>>();         // 4  <- ncu target

    lse_kernel<<<TOKS, 256>>>(amask);                      // 5
    final_kernel<<<1, 512>>>(amask, adv, out);             // 6
}

// round 12
// speedup vs baseline: 2.7917x; 1.0645x over previous
#include <cuda_runtime.h>
#include <cuda_fp16.h>
#include <math.h>
#include <stdint.h>

// Problem constants
#define G_  4
#define S_  512
#define H_  2048
#define V_  151936
#define M_  (G_*S_)              // 2048
#define TOKS (G_*(S_-1))         // 2044
#define NT2 594                  // ceil(V/256) n-tiles of 256 (last is ragged)

// GEMM tiling (fp16: K-chunk = 64 elements = 128 bytes/row)
#define BM 128
#define BN 256
#define KT 64
#define NCH (H_/KT)              // 32 k-chunks
#define ASTR 144                 // smem bytes per row (pad, conflict-free)
#define A_ST (BM*ASTR)           // 18432
#define B_ST (BN*ASTR)           // 36864
#define STG  (A_ST+B_ST)         // 55296 per stage
#define NSTAGE 2                 // 110592 B dynamic smem -> 2 CTAs/SM

// ---------------- scratch (no allocs -> __device__ globals) ------------------
__device__ __half g_Whf[(size_t)(V_+128)*H_];   // fp16 W, zero-padded tail rows
__device__ __half g_Ahf[(size_t)M_*H_];         // fp16 hidden
__device__ float g_pmax[(size_t)NT2*M_];
__device__ float g_psum[(size_t)NT2*M_];
__device__ float g_labeldot[TOKS];
__device__ float g_tokloss[TOKS];

// ---------------- helpers ----------------------------------------------------
__device__ __forceinline__ uint32_t smem_u32(const void* p) {
    uint32_t a;
    asm("{ .reg .u64 t; cvta.to.shared.u64 t, %1; cvt.u32.u64 %0, t; }" : "=r"(a) : "l"(p));
    return a;
}
__device__ __forceinline__ void cp16(uint32_t dst, const void* src) {
    asm volatile("cp.async.cg.shared.global [%0], [%1], 16;"
                 :: "r"(dst), "l"(__cvta_generic_to_global(src)) : "memory");
}
__device__ __forceinline__ void cp_commit() {
    asm volatile("cp.async.commit_group;" ::: "memory");
}
__device__ __forceinline__ void cp_wait1() {
    asm volatile("cp.async.wait_group 1;" ::: "memory");
}
__device__ __forceinline__ void ldmx4(uint32_t* r, uint32_t addr) {
    asm volatile("ldmatrix.sync.aligned.m8n8.x4.shared.b16 {%0,%1,%2,%3}, [%4];"
                 : "=r"(r[0]), "=r"(r[1]), "=r"(r[2]), "=r"(r[3]) : "r"(addr));
}
// fp16 inputs, fp16 accumulate
__device__ __forceinline__ void mma_h(uint32_t* d, const uint32_t* a, uint32_t b0, uint32_t b1) {
    asm volatile(
        "mma.sync.aligned.m16n8k16.row.col.f16.f16.f16.f16 "
        "{%0,%1}, {%2,%3,%4,%5}, {%6,%7}, {%0,%1};"
        : "+r"(d[0]), "+r"(d[1])
        : "r"(a[0]), "r"(a[1]), "r"(a[2]), "r"(a[3]), "r"(b0), "r"(b1));
}

// ---------------- fp32 -> fp16 conversion ------------------------------------
__global__ void convW_kernel(const float* __restrict__ src) {
    size_t n8 = (size_t)V_*(H_/8);
    size_t stride = (size_t)gridDim.x*blockDim.x;
    const float4* s4 = (const float4*)src;
    uint4* d4 = (uint4*)g_Whf;
    for (size_t i = (size_t)blockIdx.x*blockDim.x + threadIdx.x; i < n8; i += stride) {
        float4 f0 = s4[2*i], f1 = s4[2*i+1];
        __half2 h0 = __float22half2_rn(make_float2(f0.x, f0.y));
        __half2 h1 = __float22half2_rn(make_float2(f0.z, f0.w));
        __half2 h2 = __float22half2_rn(make_float2(f1.x, f1.y));
        __half2 h3 = __float22half2_rn(make_float2(f1.z, f1.w));
        uint4 u;
        u.x = *(unsigned*)&h0; u.y = *(unsigned*)&h1;
        u.z = *(unsigned*)&h2; u.w = *(unsigned*)&h3;
        d4[i] = u;
    }
}
__global__ void convA_kernel(const float* __restrict__ src) {
    size_t i = (size_t)blockIdx.x*blockDim.x + threadIdx.x;
    size_t n8 = (size_t)M_*(H_/8);
    if (i >= n8) return;
    const float4* s4 = (const float4*)src;
    float4 f0 = s4[2*i], f1 = s4[2*i+1];
    __half2 h0 = __float22half2_rn(make_float2(f0.x, f0.y));
    __half2 h1 = __float22half2_rn(make_float2(f0.z, f0.w));
    __half2 h2 = __float22half2_rn(make_float2(f1.x, f1.y));
    __half2 h3 = __float22half2_rn(make_float2(f1.z, f1.w));
    uint4 u;
    u.x = *(unsigned*)&h0; u.y = *(unsigned*)&h1;
    u.z = *(unsigned*)&h2; u.w = *(unsigned*)&h3;
    ((uint4*)g_Ahf)[i] = u;
}

// ---------------- GEMM (128x256 fp16/f16) + online softmax partials ----------
// 256 threads, 8 warps (2x4), warp tile 64x64, cp.async 2-stage pipeline,
// 2 CTAs per SM for inter-CTA overlap across barriers/epilogues/waves.
__device__ __forceinline__ void load_stage(uint32_t sbase, int s, int c,
                                           const __half* gA,
                                           const __half* gB, int tid) {
    uint32_t sa = sbase + s*STG;
    int k0 = c*KT;
    // A: 128 rows x 128 bytes = 1024 cp16
    #pragma unroll
    for (int i = 0; i < 4; i++) {
        int t = tid + i*256, r = t >> 3, ch = t & 7;
        cp16(sa + r*ASTR + ch*16, gA + (size_t)r*H_ + k0 + ch*8);
    }
    // B: 256 rows x 128 bytes = 2048 cp16
    uint32_t sb = sa + A_ST;
    #pragma unroll
    for (int i = 0; i < 8; i++) {
        int t = tid + i*256, r = t >> 3, ch = t & 7;
        cp16(sb + r*ASTR + ch*16, gB + (size_t)r*H_ + k0 + ch*8);
    }
}

__global__ __launch_bounds__(256, 2) void gemm_lse_kernel() {
    extern __shared__ __align__(128) char smem[];
    const int tid  = threadIdx.x;
    const int lane = tid & 31;
    const int w    = tid >> 5;
    const int wm   = w >> 2;      // 0..1 (64-row slices)
    const int wn   = w & 3;       // 0..3 (64-col slices)
    const int mt   = blockIdx.x;  // 0..15
    const int bt   = blockIdx.y;  // 0..593
    const uint32_t sbase = smem_u32(smem);

    const __half* gA = g_Ahf + (size_t)mt*BM*H_;
    const __half* gB = g_Whf + (size_t)bt*BN*H_;

    uint32_t acc[4][8][2];        // fp16x2 pairs: [0]=(c0,c1)@row r, [1]=(c2,c3)@row r+8
    #pragma unroll
    for (int i = 0; i < 4; i++)
        #pragma unroll
        for (int j = 0; j < 8; j++) { acc[i][j][0] = 0u; acc[i][j][1] = 0u; }

    // ldmatrix per-lane byte offsets
    uint32_t aoff[4], boff[4];
    {
        int rowA = wm*64 + ((lane >> 3) & 1)*8 + (lane & 7);
        int colA = (lane >> 4)*16;            // bytes (8 fp16)
        #pragma unroll
        for (int i = 0; i < 4; i++) aoff[i] = (uint32_t)((rowA + i*16)*ASTR + colA);
        int mm = lane >> 3, j2 = mm >> 1, cs = mm & 1;
        int rowB = wn*64 + j2*8 + (lane & 7);
        #pragma unroll
        for (int jj = 0; jj < 4; jj++)
            boff[jj] = (uint32_t)(A_ST + (rowB + jj*16)*ASTR + cs*16);
    }

    load_stage(sbase, 0, 0, gA, gB, tid); cp_commit();
    load_stage(sbase, 1, 1, gA, gB, tid); cp_commit();

    for (int c = 0; c < NCH; c++) {
        const int s = c & 1;
        cp_wait1();                 // chunk c landed
        __syncthreads();
        uint32_t sa = sbase + s*STG;
        #pragma unroll
        for (int ks = 0; ks < 4; ks++) {
            uint32_t kb = ks*32;              // 16 fp16 = 32 bytes
            uint32_t af[4][4], bf[4][4];
            #pragma unroll
            for (int i = 0; i < 4; i++) ldmx4(af[i], sa + aoff[i] + kb);
            #pragma unroll
            for (int jj = 0; jj < 4; jj++) ldmx4(bf[jj], sa + boff[jj] + kb);
            #pragma unroll
            for (int i = 0; i < 4; i++)
                #pragma unroll
                for (int j = 0; j < 8; j++)
                    mma_h(acc[i][j], af[i], bf[j >> 1][(j & 1)*2], bf[j >> 1][(j & 1)*2 + 1]);
        }
        __syncthreads();            // everyone done reading stage s
        if (c + 2 < NCH) load_stage(sbase, s, c + 2, gA, gB, tid);
        cp_commit();
    }
    __syncthreads();

    // ---- epilogue: per-row max + sumexp over this CTA's 256 columns ----
    const bool dead = (bt == NT2 - 1) && (wn >= 2);   // ragged tail mask
    float* redM = (float*)smem;          // [128][4]
    float* redS = redM + 512;            // [128][4]

    #pragma unroll
    for (int i = 0; i < 4; i++) {
        float v0[16], v1[16];
        #pragma unroll
        for (int j = 0; j < 8; j++) {
            float2 p0 = __half22float2(*(const __half2*)&acc[i][j][0]);
            float2 p1 = __half22float2(*(const __half2*)&acc[i][j][1]);
            v0[2*j] = p0.x; v0[2*j+1] = p0.y;
            v1[2*j] = p1.x; v1[2*j+1] = p1.y;
        }
        float mx0 = -INFINITY, mx1 = -INFINITY;
        #pragma unroll
        for (int q = 0; q < 16; q++) {
            mx0 = fmaxf(mx0, v0[q]);
            mx1 = fmaxf(mx1, v1[q]);
        }
        #pragma unroll
        for (int o = 1; o < 4; o <<= 1) {
            mx0 = fmaxf(mx0, __shfl_xor_sync(0xffffffffu, mx0, o));
            mx1 = fmaxf(mx1, __shfl_xor_sync(0xffffffffu, mx1, o));
        }
        float s0 = 0.f, s1 = 0.f;
        #pragma unroll
        for (int q = 0; q < 16; q++) {
            s0 += __expf(v0[q] - mx0);
            s1 += __expf(v1[q] - mx1);
        }
        #pragma unroll
        for (int o = 1; o < 4; o <<= 1) {
            s0 += __shfl_xor_sync(0xffffffffu, s0, o);
            s1 += __shfl_xor_sync(0xffffffffu, s1, o);
        }
        if (dead) { mx0 = -INFINITY; mx1 = -INFINITY; s0 = 0.f; s1 = 0.f; }
        if ((lane & 3) == 0) {
            int r = wm*64 + i*16 + (lane >> 2);
            redM[r*4 + wn]     = mx0;  redS[r*4 + wn]     = s0;
            redM[(r+8)*4 + wn] = mx1;  redS[(r+8)*4 + wn] = s1;
        }
    }
    __syncthreads();

    if (tid < 128) {
        float m = redM[tid*4 + 0];
        #pragma unroll
        for (int t = 1; t < 4; t++) m = fmaxf(m, redM[tid*4 + t]);
        float sv = 0.f;
        #pragma unroll
        for (int t = 0; t < 4; t++) {
            float pm = redM[tid*4 + t];
            if (pm > -INFINITY) sv += redS[tid*4 + t] * __expf(pm - m);
        }
        size_t idx = (size_t)bt * M_ + (mt*128 + tid);
        g_pmax[idx] = m;
        g_psum[idx] = sv;
    }
}

// ---------------- exact fp32 label logits ------------------------------------
__global__ void labeldot_kernel(const float* __restrict__ hs,
                                const float* __restrict__ Wlm,
                                const int*   __restrict__ ids) {
    int b = blockIdx.x;
    int g = b / (S_-1), t = b % (S_-1);
    int m = g*S_ + t;
    int label = ids[g*S_ + t + 1];
    const float4* h4 = (const float4*)(hs  + (size_t)m*H_);
    const float4* w4 = (const float4*)(Wlm + (size_t)label*H_);
    float p = 0.f;
    for (int i = threadIdx.x; i < H_/4; i += 256) {
        float4 a = h4[i], bb = w4[i];
        p += a.x*bb.x + a.y*bb.y + a.z*bb.z + a.w*bb.w;
    }
    __shared__ float red[256];
    red[threadIdx.x] = p; __syncthreads();
    for (int s = 128; s > 0; s >>= 1) {
        if (threadIdx.x < s) red[threadIdx.x] += red[threadIdx.x + s];
        __syncthreads();
    }
    if (threadIdx.x == 0) g_labeldot[b] = red[0];
}

// ---------------- combine partials -> logsumexp -> token loss ----------------
__global__ void lse_kernel(const float* __restrict__ amask) {
    int b = blockIdx.x;
    int g = b / (S_-1), t = b % (S_-1);
    int m = g*S_ + t;

    float mx = -INFINITY, sm = 0.f;
    for (int nt = threadIdx.x; nt < NT2; nt += 256) {
        float pm = g_pmax[(size_t)nt*M_ + m];
        float ps = g_psum[(size_t)nt*M_ + m];
        if (pm > mx) { sm = sm*__expf(mx - pm) + ps; mx = pm; }
        else         { sm += ps*__expf(pm - mx); }
    }
    __shared__ float rm[256], rs[256];
    rm[threadIdx.x] = mx; rs[threadIdx.x] = sm;
    __syncthreads();
    for (int s = 128; s > 0; s >>= 1) {
        if (threadIdx.x < s) {
            float m1 = rm[threadIdx.x],     s1 = rs[threadIdx.x];
            float m2 = rm[threadIdx.x + s], s2 = rs[threadIdx.x + s];
            float M  = fmaxf(m1, m2);
            rm[threadIdx.x] = M;
            rs[threadIdx.x] = s1*__expf(m1 - M) + s2*__expf(m2 - M);
        }
        __syncthreads();
    }
    if (threadIdx.x == 0) {
        float lse = rm[0] + logf(rs[0]);
        g_tokloss[b] = (lse - g_labeldot[b]) * amask[g*S_ + t + 1];
    }
}

// ---------------- final weighted mean ----------------------------------------
__global__ void final_kernel(const float* __restrict__ amask,
                             const float* __restrict__ adv,
                             float* __restrict__ out) {
    __shared__ float sl[512], sk[512];
    int tid = threadIdx.x;
    int g = tid >> 7, idx = tid & 127;
    float pl = 0.f, pm = 0.f;
    for (int j = idx; j < S_-1; j += 128) {
        pl += g_tokloss[g*(S_-1) + j];
        pm += amask[g*S_ + 1 + j];
    }
    sl[tid] = pl; sk[tid] = pm;
    __syncthreads();
    for (int s = 64; s > 0; s >>= 1) {
        if (idx < s) { sl[tid] += sl[tid + s]; sk[tid] += sk[tid + s]; }
        __syncthreads();
    }
    if (tid == 0) {
        float acc = 0.f;
        for (int gg = 0; gg < G_; gg++) {
            float len = fmaxf(sk[gg*128], 1.0f);
            acc += (sl[gg*128] / len) * adv[gg];
        }
        out[0] = acc / (float)G_;
    }
}

// ---------------- launch ------------------------------------------------------
// Gemm is our 4th launch so ncu's "-s 5 -c 1" lands on it.
extern "C" void kernel_launch(void* const* d_in, const int* in_sizes, int n_in,
                              void* d_out, int out_size) {
    const float* hs    = (const float*)d_in[0];
    const float* Wlm   = (const float*)d_in[1];
    const int*   ids   = (const int*)  d_in[2];
    const float* amask = (const float*)d_in[3];
    const float* adv   = (const float*)d_in[4];
    float* out = (float*)d_out;

    cudaFuncSetAttribute(gemm_lse_kernel,
                         cudaFuncAttributeMaxDynamicSharedMemorySize,
                         NSTAGE*STG);

    labeldot_kernel<<<TOKS, 256>>>(hs, Wlm, ids);          // 1
    convA_kernel<<<(M_*(H_/8) + 255)/256, 256>>>(hs);      // 2
    convW_kernel<<<4096, 256>>>(Wlm);                      // 3

    dim3 grid(M_/BM, NT2);               // x = m-tile fast -> B reused via L2
    gemm_lse_kernel<<<grid, 256, NSTAGE*STG>>>();          // 4  <- ncu target

    lse_kernel<<<TOKS, 256>>>(amask);                      // 5
    final_kernel<<<1, 512>>>(amask, adv, out);             // 6
}

// round 13
// speedup vs baseline: 2.9584x; 1.0597x over previous
#include <cuda_runtime.h>
#include <cuda_fp16.h>
#include <math.h>
#include <stdint.h>

// Problem constants
#define G_  4
#define S_  512
#define H_  2048
#define V_  151936
#define M_  (G_*S_)              // 2048
#define TOKS (G_*(S_-1))         // 2044
#define NT2 594                  // ceil(V/256) n-tiles of 256 (last is ragged)

// GEMM tiling (fp16: K-chunk = 64 elements = 128 bytes/row)
#define BM 256
#define BN 256
#define KT 64
#define NCH (H_/KT)              // 32 k-chunks
#define ASTR 144                 // smem bytes per row (pad, conflict-free)
#define A_ST (BM*ASTR)           // 36864
#define B_ST (BN*ASTR)           // 36864
#define STG  (A_ST+B_ST)         // 73728 per stage
#define NSTAGE 3                 // 221184 B dynamic smem, 1 CTA/SM
#define NTHR 512                 // 16 warps: 4x4 grid, warp tile 64x64

// ---------------- scratch (no allocs -> __device__ globals) ------------------
__device__ __half g_Whf[(size_t)(V_+128)*H_];   // fp16 W, zero-padded tail rows
__device__ __half g_Ahf[(size_t)M_*H_];         // fp16 hidden
__device__ float g_pmax[(size_t)NT2*M_];
__device__ float g_psum[(size_t)NT2*M_];
__device__ float g_labeldot[TOKS];
__device__ float g_tokloss[TOKS];

// ---------------- helpers ----------------------------------------------------
__device__ __forceinline__ uint32_t smem_u32(const void* p) {
    uint32_t a;
    asm("{ .reg .u64 t; cvta.to.shared.u64 t, %1; cvt.u32.u64 %0, t; }" : "=r"(a) : "l"(p));
    return a;
}
__device__ __forceinline__ void cp16(uint32_t dst, const void* src) {
    asm volatile("cp.async.cg.shared.global [%0], [%1], 16;"
                 :: "r"(dst), "l"(__cvta_generic_to_global(src)) : "memory");
}
__device__ __forceinline__ void cp_commit() {
    asm volatile("cp.async.commit_group;" ::: "memory");
}
__device__ __forceinline__ void cp_wait1() {
    asm volatile("cp.async.wait_group 1;" ::: "memory");
}
__device__ __forceinline__ void ldmx4(uint32_t* r, uint32_t addr) {
    asm volatile("ldmatrix.sync.aligned.m8n8.x4.shared.b16 {%0,%1,%2,%3}, [%4];"
                 : "=r"(r[0]), "=r"(r[1]), "=r"(r[2]), "=r"(r[3]) : "r"(addr));
}
// fp16 inputs, fp16 accumulate
__device__ __forceinline__ void mma_h(uint32_t* d, const uint32_t* a, uint32_t b0, uint32_t b1) {
    asm volatile(
        "mma.sync.aligned.m16n8k16.row.col.f16.f16.f16.f16 "
        "{%0,%1}, {%2,%3,%4,%5}, {%6,%7}, {%0,%1};"
        : "+r"(d[0]), "+r"(d[1])
        : "r"(a[0]), "r"(a[1]), "r"(a[2]), "r"(a[3]), "r"(b0), "r"(b1));
}

// ---------------- fp32 -> fp16 conversion ------------------------------------
__global__ void convW_kernel(const float* __restrict__ src) {
    size_t n8 = (size_t)V_*(H_/8);
    size_t stride = (size_t)gridDim.x*blockDim.x;
    const float4* s4 = (const float4*)src;
    uint4* d4 = (uint4*)g_Whf;
    for (size_t i = (size_t)blockIdx.x*blockDim.x + threadIdx.x; i < n8; i += stride) {
        float4 f0 = s4[2*i], f1 = s4[2*i+1];
        __half2 h0 = __float22half2_rn(make_float2(f0.x, f0.y));
        __half2 h1 = __float22half2_rn(make_float2(f0.z, f0.w));
        __half2 h2 = __float22half2_rn(make_float2(f1.x, f1.y));
        __half2 h3 = __float22half2_rn(make_float2(f1.z, f1.w));
        uint4 u;
        u.x = *(unsigned*)&h0; u.y = *(unsigned*)&h1;
        u.z = *(unsigned*)&h2; u.w = *(unsigned*)&h3;
        d4[i] = u;
    }
}
__global__ void convA_kernel(const float* __restrict__ src) {
    size_t i = (size_t)blockIdx.x*blockDim.x + threadIdx.x;
    size_t n8 = (size_t)M_*(H_/8);
    if (i >= n8) return;
    const float4* s4 = (const float4*)src;
    float4 f0 = s4[2*i], f1 = s4[2*i+1];
    __half2 h0 = __float22half2_rn(make_float2(f0.x, f0.y));
    __half2 h1 = __float22half2_rn(make_float2(f0.z, f0.w));
    __half2 h2 = __float22half2_rn(make_float2(f1.x, f1.y));
    __half2 h3 = __float22half2_rn(make_float2(f1.z, f1.w));
    uint4 u;
    u.x = *(unsigned*)&h0; u.y = *(unsigned*)&h1;
    u.z = *(unsigned*)&h2; u.w = *(unsigned*)&h3;
    ((uint4*)g_Ahf)[i] = u;
}

// ---------------- GEMM (256x256 fp16/f16) + online softmax partials ----------
// 512 threads, 16 warps (4x4), warp tile 64x64, cp.async 3-stage pipeline.
__device__ __forceinline__ void load_stage(uint32_t sbase, int s, int c,
                                           const __half* gA,
                                           const __half* gB, int tid) {
    uint32_t sa = sbase + s*STG;
    int k0 = c*KT;
    // A: 256 rows x 128 bytes = 2048 cp16
    #pragma unroll
    for (int i = 0; i < 4; i++) {
        int t = tid + i*NTHR, r = t >> 3, ch = t & 7;
        cp16(sa + r*ASTR + ch*16, gA + (size_t)r*H_ + k0 + ch*8);
    }
    // B: 256 rows x 128 bytes = 2048 cp16
    uint32_t sb = sa + A_ST;
    #pragma unroll
    for (int i = 0; i < 4; i++) {
        int t = tid + i*NTHR, r = t >> 3, ch = t & 7;
        cp16(sb + r*ASTR + ch*16, gB + (size_t)r*H_ + k0 + ch*8);
    }
}

__global__ __launch_bounds__(NTHR, 1) void gemm_lse_kernel() {
    extern __shared__ __align__(128) char smem[];
    const int tid  = threadIdx.x;
    const int lane = tid & 31;
    const int w    = tid >> 5;
    const int wm   = w >> 2;      // 0..3 (64-row slices)
    const int wn   = w & 3;       // 0..3 (64-col slices)
    const int mt   = blockIdx.x;  // 0..7
    const int bt   = blockIdx.y;  // 0..593
    const uint32_t sbase = smem_u32(smem);

    const __half* gA = g_Ahf + (size_t)mt*BM*H_;
    const __half* gB = g_Whf + (size_t)bt*BN*H_;

    uint32_t acc[4][8][2];        // fp16x2 pairs: [0]=(c0,c1)@row r, [1]=(c2,c3)@row r+8
    #pragma unroll
    for (int i = 0; i < 4; i++)
        #pragma unroll
        for (int j = 0; j < 8; j++) { acc[i][j][0] = 0u; acc[i][j][1] = 0u; }

    // ldmatrix per-lane byte offsets
    uint32_t aoff[4], boff[4];
    {
        int rowA = wm*64 + ((lane >> 3) & 1)*8 + (lane & 7);
        int colA = (lane >> 4)*16;            // bytes (8 fp16)
        #pragma unroll
        for (int i = 0; i < 4; i++) aoff[i] = (uint32_t)((rowA + i*16)*ASTR + colA);
        int mm = lane >> 3, j2 = mm >> 1, cs = mm & 1;
        int rowB = wn*64 + j2*8 + (lane & 7);
        #pragma unroll
        for (int jj = 0; jj < 4; jj++)
            boff[jj] = (uint32_t)(A_ST + (rowB + jj*16)*ASTR + cs*16);
    }

    load_stage(sbase, 0, 0, gA, gB, tid); cp_commit();
    load_stage(sbase, 1, 1, gA, gB, tid); cp_commit();

    int s = 0;
    for (int c = 0; c < NCH; c++) {
        cp_wait1();                 // chunk c landed
        __syncthreads();            // single barrier per chunk (3-stage safe)
        uint32_t sa = sbase + s*STG;
        #pragma unroll
        for (int ks = 0; ks < 4; ks++) {
            uint32_t kb = ks*32;              // 16 fp16 = 32 bytes
            uint32_t af[4][4], bf[4][4];
            #pragma unroll
            for (int i = 0; i < 4; i++) ldmx4(af[i], sa + aoff[i] + kb);
            #pragma unroll
            for (int jj = 0; jj < 4; jj++) ldmx4(bf[jj], sa + boff[jj] + kb);
            #pragma unroll
            for (int i = 0; i < 4; i++)
                #pragma unroll
                for (int j = 0; j < 8; j++)
                    mma_h(acc[i][j], af[i], bf[j >> 1][(j & 1)*2], bf[j >> 1][(j & 1)*2 + 1]);
        }
        if (c + 2 < NCH) {
            int sn = s + 2; if (sn >= NSTAGE) sn -= NSTAGE;
            load_stage(sbase, sn, c + 2, gA, gB, tid);
        }
        cp_commit();
        if (++s == NSTAGE) s = 0;
    }
    __syncthreads();

    // ---- epilogue: per-row max + sumexp over this CTA's 256 columns ----
    const bool dead = (bt == NT2 - 1) && (wn >= 2);   // ragged tail mask
    float* redM = (float*)smem;          // [256][4]
    float* redS = redM + 1024;           // [256][4]

    #pragma unroll
    for (int i = 0; i < 4; i++) {
        float v0[16], v1[16];
        #pragma unroll
        for (int j = 0; j < 8; j++) {
            float2 p0 = __half22float2(*(const __half2*)&acc[i][j][0]);
            float2 p1 = __half22float2(*(const __half2*)&acc[i][j][1]);
            v0[2*j] = p0.x; v0[2*j+1] = p0.y;
            v1[2*j] = p1.x; v1[2*j+1] = p1.y;
        }
        float mx0 = -INFINITY, mx1 = -INFINITY;
        #pragma unroll
        for (int q = 0; q < 16; q++) {
            mx0 = fmaxf(mx0, v0[q]);
            mx1 = fmaxf(mx1, v1[q]);
        }
        #pragma unroll
        for (int o = 1; o < 4; o <<= 1) {
            mx0 = fmaxf(mx0, __shfl_xor_sync(0xffffffffu, mx0, o));
            mx1 = fmaxf(mx1, __shfl_xor_sync(0xffffffffu, mx1, o));
        }
        float s0 = 0.f, s1 = 0.f;
        #pragma unroll
        for (int q = 0; q < 16; q++) {
            s0 += __expf(v0[q] - mx0);
            s1 += __expf(v1[q] - mx1);
        }
        #pragma unroll
        for (int o = 1; o < 4; o <<= 1) {
            s0 += __shfl_xor_sync(0xffffffffu, s0, o);
            s1 += __shfl_xor_sync(0xffffffffu, s1, o);
        }
        if (dead) { mx0 = -INFINITY; mx1 = -INFINITY; s0 = 0.f; s1 = 0.f; }
        if ((lane & 3) == 0) {
            int r = wm*64 + i*16 + (lane >> 2);
            redM[r*4 + wn]     = mx0;  redS[r*4 + wn]     = s0;
            redM[(r+8)*4 + wn] = mx1;  redS[(r+8)*4 + wn] = s1;
        }
    }
    __syncthreads();

    if (tid < 256) {
        float m = redM[tid*4 + 0];
        #pragma unroll
        for (int t = 1; t < 4; t++) m = fmaxf(m, redM[tid*4 + t]);
        float sv = 0.f;
        #pragma unroll
        for (int t = 0; t < 4; t++) {
            float pm = redM[tid*4 + t];
            if (pm > -INFINITY) sv += redS[tid*4 + t] * __expf(pm - m);
        }
        size_t idx = (size_t)bt * M_ + (mt*BM + tid);
        g_pmax[idx] = m;
        g_psum[idx] = sv;
    }
}

// ---------------- exact fp32 label logits ------------------------------------
__global__ void labeldot_kernel(const float* __restrict__ hs,
                                const float* __restrict__ Wlm,
                                const int*   __restrict__ ids) {
    int b = blockIdx.x;
    int g = b / (S_-1), t = b % (S_-1);
    int m = g*S_ + t;
    int label = ids[g*S_ + t + 1];
    const float4* h4 = (const float4*)(hs  + (size_t)m*H_);
    const float4* w4 = (const float4*)(Wlm + (size_t)label*H_);
    float p = 0.f;
    for (int i = threadIdx.x; i < H_/4; i += 256) {
        float4 a = h4[i], bb = w4[i];
        p += a.x*bb.x + a.y*bb.y + a.z*bb.z + a.w*bb.w;
    }
    __shared__ float red[256];
    red[threadIdx.x] = p; __syncthreads();
    for (int s = 128; s > 0; s >>= 1) {
        if (threadIdx.x < s) red[threadIdx.x] += red[threadIdx.x + s];
        __syncthreads();
    }
    if (threadIdx.x == 0) g_labeldot[b] = red[0];
}

// ---------------- combine partials -> logsumexp -> token loss ----------------
__global__ void lse_kernel(const float* __restrict__ amask) {
    int b = blockIdx.x;
    int g = b / (S_-1), t = b % (S_-1);
    int m = g*S_ + t;

    float mx = -INFINITY, sm = 0.f;
    for (int nt = threadIdx.x; nt < NT2; nt += 256) {
        float pm = g_pmax[(size_t)nt*M_ + m];
        float ps = g_psum[(size_t)nt*M_ + m];
        if (pm > mx) { sm = sm*__expf(mx - pm) + ps; mx = pm; }
        else         { sm += ps*__expf(pm - mx); }
    }
    __shared__ float rm[256], rs[256];
    rm[threadIdx.x] = mx; rs[threadIdx.x] = sm;
    __syncthreads();
    for (int s = 128; s > 0; s >>= 1) {
        if (threadIdx.x < s) {
            float m1 = rm[threadIdx.x],     s1 = rs[threadIdx.x];
            float m2 = rm[threadIdx.x + s], s2 = rs[threadIdx.x + s];
            float M  = fmaxf(m1, m2);
            rm[threadIdx.x] = M;
            rs[threadIdx.x] = s1*__expf(m1 - M) + s2*__expf(m2 - M);
        }
        __syncthreads();
    }
    if (threadIdx.x == 0) {
        float lse = rm[0] + logf(rs[0]);
        g_tokloss[b] = (lse - g_labeldot[b]) * amask[g*S_ + t + 1];
    }
}

// ---------------- final weighted mean ----------------------------------------
__global__ void final_kernel(const float* __restrict__ amask,
                             const float* __restrict__ adv,
                             float* __restrict__ out) {
    __shared__ float sl[512], sk[512];
    int tid = threadIdx.x;
    int g = tid >> 7, idx = tid & 127;
    float pl = 0.f, pm = 0.f;
    for (int j = idx; j < S_-1; j += 128) {
        pl += g_tokloss[g*(S_-1) + j];
        pm += amask[g*S_ + 1 + j];
    }
    sl[tid] = pl; sk[tid] = pm;
    __syncthreads();
    for (int s = 64; s > 0; s >>= 1) {
        if (idx < s) { sl[tid] += sl[tid + s]; sk[tid] += sk[tid + s]; }
        __syncthreads();
    }
    if (tid == 0) {
        float acc = 0.f;
        for (int gg = 0; gg < G_; gg++) {
            float len = fmaxf(sk[gg*128], 1.0f);
            acc += (sl[gg*128] / len) * adv[gg];
        }
        out[0] = acc / (float)G_;
    }
}

// ---------------- launch ------------------------------------------------------
// Gemm is our 4th launch so ncu's "-s 5 -c 1" lands on it.
extern "C" void kernel_launch(void* const* d_in, const int* in_sizes, int n_in,
                              void* d_out, int out_size) {
    const float* hs    = (const float*)d_in[0];
    const float* Wlm   = (const float*)d_in[1];
    const int*   ids   = (const int*)  d_in[2];
    const float* amask = (const float*)d_in[3];
    const float* adv   = (const float*)d_in[4];
    float* out = (float*)d_out;

    cudaFuncSetAttribute(gemm_lse_kernel,
                         cudaFuncAttributeMaxDynamicSharedMemorySize,
                         NSTAGE*STG);

    labeldot_kernel<<<TOKS, 256>>>(hs, Wlm, ids);          // 1
    convA_kernel<<<(M_*(H_/8) + 255)/256, 256>>>(hs);      // 2
    convW_kernel<<<4096, 256>>>(Wlm);                      // 3

    dim3 grid(M_/BM, NT2);               // x = m-tile fast -> B reused via L2
    gemm_lse_kernel<<<grid, NTHR, NSTAGE*STG>>>();         // 4  <- ncu target

    lse_kernel<<<TOKS, 256>>>(amask);                      // 5
    final_kernel<<<1, 512>>>(amask, adv, out);             // 6
}